// round 13
// baseline (speedup 1.0000x reference)
#include <cuda_runtime.h>
#include <math.h>

#define GAMMA_F 1.4f
#define EPS_F   1e-6f
constexpr int B_  = 16;
constexpr int K_  = 64;
constexpr int NT_ = 128;
constexpr int NX_ = 256;
constexpr int NI_ = K_ - 1;           // 63 interfaces per batch
constexpr int N_NEWTON = 12;          // fp32 fixed point well before 12 iters

// MUFU transcendentals via inline PTX
__device__ __forceinline__ float f_lg2(float x) {
    float r;
    asm("lg2.approx.f32 %0, %1;" : "=f"(r) : "f"(x));
    return r;
}
__device__ __forceinline__ float f_ex2(float x) {
    float r;
    asm("ex2.approx.f32 %0, %1;" : "=f"(r) : "f"(x));
    return r;
}
__device__ __forceinline__ float fast_pow(float x, float e) {
    return f_ex2(e * f_lg2(x));
}

// ---------------------------------------------------------------------------
// Fused kernel: every block redundantly solves its batch's 63 Riemann
// interfaces (threads 0-62, MUFU work on an otherwise-idle pipe, overlapped
// with the front-batched coordinate loads), then runs the bias field loop.
// One launch, no global scratch round-trip, no PDL.
//
// Bias body = R10 best: thread = (pgroup, quad), 16 consecutive positions,
// 8 front-batched LDG.128, register K-tables, FMA+relu algebra, __stcs.
// ---------------------------------------------------------------------------
constexpr int THREADS = 256;
constexpr int QUADS = 16;                                // 16 quads cover K=64
constexpr int POS_PER_PG = 16;                           // consecutive positions
constexpr int POS_PER_BLOCK = (THREADS / QUADS) * POS_PER_PG;  // 256
constexpr int BLOCKS_PER_B  = (NT_ * NX_) / POS_PER_BLOCK;     // 128

__global__ __launch_bounds__(THREADS)
void fused_bias_kernel(const float* __restrict__ xs,
                       const float* __restrict__ ks,
                       const float* __restrict__ ks_v,
                       const float* __restrict__ ks_p,
                       const float* __restrict__ pieces_mask,
                       const float* __restrict__ t_coords,
                       const float* __restrict__ x_coords,
                       float* __restrict__ out) {
    __shared__ float s_xd[K_];   // s_xd[k] = xs[b,k+1] for k<63; s_xd[63] = 0 (pad)
    __shared__ float s_sl[NI_];
    __shared__ float s_sr[K_];   // s_sr[63] = +1e30 (pad: kills pen_left at k=63)
    __shared__ float s_m [K_];

    int b        = blockIdx.x >> 7;        // / BLOCKS_PER_B (=128)
    int blockInB = blockIdx.x & (BLOCKS_PER_B - 1);
    int t = threadIdx.x;

    // ---- Front-batch ALL coordinate loads first (8x LDG.128, MLP=8).
    // They are consumed only after the Newton phase, so their latency is
    // fully hidden under the compute below.
    size_t base   = (size_t)b * (NT_ * NX_) + (size_t)blockInB * POS_PER_BLOCK;
    int    pg     = t >> 4;
    size_t pbase  = base + (size_t)pg * POS_PER_PG;
    const float4* t4 = reinterpret_cast<const float4*>(t_coords + pbase);
    const float4* x4 = reinterpret_cast<const float4*>(x_coords + pbase);
    float4 T[4], X[4];
    #pragma unroll
    for (int c = 0; c < 4; ++c) { T[c] = __ldg(t4 + c); X[c] = __ldg(x4 + c); }

    // ---- Per-block Riemann solve: thread j < 63 handles interface j of b.
    if (t < NI_) {
        int j = t;
        const float gm1 = 0.4f;
        const float gp1 = 2.4f;
        const float exp_rare = gm1 / (2.0f * GAMMA_F);               // 1/7
        const float neg_exp  = -(GAMMA_F + 1.0f) / (2.0f * GAMMA_F); // -6/7

        float rho_L = ks  [b * K_ + j];
        float rho_R = ks  [b * K_ + j + 1];
        float u_L   = ks_v[b * K_ + j];
        float u_R   = ks_v[b * K_ + j + 1];
        float p_L   = ks_p[b * K_ + j];
        float p_R   = ks_p[b * K_ + j + 1];

        float pLc = fmaxf(p_L, EPS_F);
        float pRc = fmaxf(p_R, EPS_F);

        float c_L = sqrtf(fmaxf(GAMMA_F * p_L / fmaxf(rho_L, EPS_F), EPS_F));
        float c_R = sqrtf(fmaxf(GAMMA_F * p_R / fmaxf(rho_R, EPS_F), EPS_F));
        float A_L = 2.0f / (gp1 * fmaxf(rho_L, EPS_F));
        float A_R = 2.0f / (gp1 * fmaxf(rho_R, EPS_F));
        float B_L = gm1 / gp1 * p_L;
        float B_R = gm1 / gp1 * p_R;
        float invpL = __fdividef(1.0f, pLc);
        float invpR = __fdividef(1.0f, pRc);
        float cg_L  = c_L * invpL * (1.0f / GAMMA_F);
        float cg_R  = c_R * invpR * (1.0f / GAMMA_F);
        float tfc_L = 2.0f * c_L / gm1;
        float tfc_R = 2.0f * c_R / gm1;

        float du  = u_R - u_L;
        float num = c_L + c_R - 0.5f * gm1 * du;
        float den = c_L * fast_pow(pLc, -exp_rare) + c_R * fast_pow(pRc, -exp_rare);
        float r   = __fdividef(num, den);
        float r2  = r * r;
        float r4  = r2 * r2;
        float p_star = fmaxf(r4 * r2 * r, EPS_F);       // r^7

        #pragma unroll 1
        for (int it = 0; it < N_NEWTON; ++it) {
            float fL, dfL, fR, dfR;
            {
                float denom    = fmaxf(p_star + B_L, EPS_F);
                float sqrt_AoD = sqrtf(fmaxf(__fdividef(A_L, denom), EPS_F));
                float dl       = p_star - p_L;
                float f_shock  = dl * sqrt_AoD;
                float df_shock = sqrt_AoD * (1.0f - dl * __fdividef(0.5f, denom));
                float pratio   = fmaxf(p_star * invpL, EPS_F);
                float l2       = f_lg2(pratio);
                float f_rare   = tfc_L * (f_ex2(exp_rare * l2) - 1.0f);
                float df_rare  = cg_L * f_ex2(neg_exp * l2);
                bool  shock    = p_star > p_L;
                fL  = shock ? f_shock  : f_rare;
                dfL = shock ? df_shock : df_rare;
            }
            {
                float denom    = fmaxf(p_star + B_R, EPS_F);
                float sqrt_AoD = sqrtf(fmaxf(__fdividef(A_R, denom), EPS_F));
                float dr       = p_star - p_R;
                float f_shock  = dr * sqrt_AoD;
                float df_shock = sqrt_AoD * (1.0f - dr * __fdividef(0.5f, denom));
                float pratio   = fmaxf(p_star * invpR, EPS_F);
                float l2       = f_lg2(pratio);
                float f_rare   = tfc_R * (f_ex2(exp_rare * l2) - 1.0f);
                float df_rare  = cg_R * f_ex2(neg_exp * l2);
                bool  shock    = p_star > p_R;
                fR  = shock ? f_shock  : f_rare;
                dfR = shock ? df_shock : df_rare;
            }
            float residual = fL + fR + du;
            float jacobian = fmaxf(dfL + dfR, EPS_F);
            p_star = fmaxf(p_star - __fdividef(residual, jacobian), EPS_F);
        }

        const float gp1_o_2g = gp1 / (2.0f * GAMMA_F);
        float sig1 = u_L - c_L * sqrtf(fmaxf(1.0f + gp1_o_2g * (p_star * invpL - 1.0f), EPS_F));
        float speed_left = (p_star > p_L) ? sig1 : (u_L - c_L);
        float sig3 = u_R + c_R * sqrtf(fmaxf(1.0f + gp1_o_2g * (p_star * invpR - 1.0f), EPS_F));
        float speed_right = (p_star > p_R) ? sig3 : (u_R + c_R);

        s_sl[j] = speed_left;
        s_sr[j] = speed_right;
        s_xd[j] = xs[b * (K_ + 1) + j + 1];
    }
    if (t == NI_) { s_xd[NI_] = 0.0f; s_sr[NI_] = 1e30f; }
    if (t < K_) s_m[t] = pieces_mask[b * K_ + t];
    __syncthreads();

    // ---- Per-thread register tables ----
    int q  = t & (QUADS - 1);
    int k0 = q << 2;

    float xda[5];                          // xd[k0-1 .. k0+3]
    float slv[4], srv[4], negm[4], b0[4];  // sl[k-1], sr[k], -m[k], bias0[k]
    xda[0] = (k0 == 0) ? 0.0f : s_xd[k0 - 1];
    slv[0] = (k0 == 0) ? -1e30f : s_sl[k0 - 1];   // sentinel: pen_right(k=0)=0
    #pragma unroll
    for (int i = 1; i < 5; ++i) xda[i] = s_xd[k0 + i - 1];
    #pragma unroll
    for (int kk = 1; kk < 4; ++kk) slv[kk] = s_sl[k0 + kk - 1];
    #pragma unroll
    for (int kk = 0; kk < 4; ++kk) {
        srv[kk] = s_sr[k0 + kk];
        float m = s_m[k0 + kk];
        negm[kk] = -m;
        b0[kk]   = (m == 0.0f) ? -1e9f : 0.0f;
    }

    float* op = out + pbase * K_ + k0;

    // ---- Bias main loop ----
    #pragma unroll
    for (int c = 0; c < 4; ++c) {
        float tts[4] = {T[c].x, T[c].y, T[c].z, T[c].w};
        float xxs[4] = {X[c].x, X[c].y, X[c].z, X[c].w};

        #pragma unroll
        for (int p = 0; p < 4; ++p) {
            float te  = tts[p] + EPS_F;
            float xx  = xxs[p];
            float inv = __fdividef(1.0f, te);

            float d[5];
            #pragma unroll
            for (int i = 0; i < 5; ++i) d[i] = xx - xda[i];

            float vals[4];
            #pragma unroll
            for (int kk = 0; kk < 4; ++kk) {
                float pl = fmaxf(fmaf(-srv[kk], te,  d[kk + 1]), 0.0f);
                float pr = fmaxf(fmaf( slv[kk], te, -d[kk]),     0.0f);
                vals[kk] = fmaf((pl + pr) * inv, negm[kk], b0[kk]);
            }
            __stcs(reinterpret_cast<float4*>(op + (size_t)(c * 4 + p) * K_),
                   make_float4(vals[0], vals[1], vals[2], vals[3]));
        }
    }
}

// ---------------------------------------------------------------------------
// Launch. Inputs: 0:xs 1:ks 2:ks_v 3:ks_p 4:pieces_mask 5:t_coords 6:x_coords
// Single fused kernel launch.
// ---------------------------------------------------------------------------
extern "C" void kernel_launch(void* const* d_in, const int* in_sizes, int n_in,
                              void* d_out, int out_size) {
    const float* xs          = (const float*)d_in[0];
    const float* ks          = (const float*)d_in[1];
    const float* ks_v        = (const float*)d_in[2];
    const float* ks_p        = (const float*)d_in[3];
    const float* pieces_mask = (const float*)d_in[4];
    const float* t_coords    = (const float*)d_in[5];
    const float* x_coords    = (const float*)d_in[6];
    float* out = (float*)d_out;

    fused_bias_kernel<<<B_ * BLOCKS_PER_B, THREADS>>>(   // 2048 blocks
        xs, ks, ks_v, ks_p, pieces_mask, t_coords, x_coords, out);
}

// round 14
// speedup vs baseline: 1.1244x; 1.1244x over previous
#include <cuda_runtime.h>
#include <math.h>

#define GAMMA_F 1.4f
#define EPS_F   1e-6f
constexpr int B_  = 16;
constexpr int K_  = 64;
constexpr int NT_ = 128;
constexpr int NX_ = 256;
constexpr int NI_ = K_ - 1;           // 63 interfaces per batch
constexpr int N_NEWTON = 12;          // fp32 fixed point well before 12 iters

// MUFU transcendentals via inline PTX
__device__ __forceinline__ float f_lg2(float x) {
    float r;
    asm("lg2.approx.f32 %0, %1;" : "=f"(r) : "f"(x));
    return r;
}
__device__ __forceinline__ float f_ex2(float x) {
    float r;
    asm("ex2.approx.f32 %0, %1;" : "=f"(r) : "f"(x));
    return r;
}
__device__ __forceinline__ float fast_pow(float x, float e) {
    return f_ex2(e * f_lg2(x));
}

// ---------------------------------------------------------------------------
// Persistent fused kernel: each block owns TWO contiguous 256-position tiles
// of one batch. The per-batch Riemann Newton solve (threads 0-62) is paid
// ONCE per block and amortized over both tiles; tile-1 coordinate loads are
// issued before the Newton phase so their latency hides under it.
// Bias body = R10 best: thread = (pgroup, quad), 16 consecutive positions,
// 8 front-batched LDG.128 per tile, register K-tables, FMA+relu, __stcs.
// ---------------------------------------------------------------------------
constexpr int THREADS = 256;
constexpr int QUADS = 16;                                // 16 quads cover K=64
constexpr int POS_PER_PG = 16;                           // consecutive positions
constexpr int POS_PER_TILE = (THREADS / QUADS) * POS_PER_PG;   // 256
constexpr int TILES_PER_BLOCK = 2;
constexpr int TILES_PER_B = (NT_ * NX_) / POS_PER_TILE;        // 128
constexpr int BLOCKS_PER_B = TILES_PER_B / TILES_PER_BLOCK;    // 64
constexpr int GRID = B_ * BLOCKS_PER_B;                        // 1024

__global__ __launch_bounds__(THREADS)
void fused_bias_kernel(const float* __restrict__ xs,
                       const float* __restrict__ ks,
                       const float* __restrict__ ks_v,
                       const float* __restrict__ ks_p,
                       const float* __restrict__ pieces_mask,
                       const float* __restrict__ t_coords,
                       const float* __restrict__ x_coords,
                       float* __restrict__ out) {
    __shared__ float s_xd[K_];   // s_xd[k] = xs[b,k+1] for k<63; s_xd[63] = 0 (pad)
    __shared__ float s_sl[NI_];
    __shared__ float s_sr[K_];   // s_sr[63] = +1e30 (pad: kills pen_left at k=63)
    __shared__ float s_m [K_];

    int b       = blockIdx.x >> 6;               // / BLOCKS_PER_B (=64)
    int chunk   = blockIdx.x & (BLOCKS_PER_B - 1);
    int tile0   = chunk * TILES_PER_BLOCK;       // first of 2 tiles in batch b
    int t = threadIdx.x;
    int pg = t >> 4;

    // ---- Issue tile-1 coordinate loads FIRST (8x LDG.128, MLP=8).
    // Consumed only after the Newton phase -> latency fully hidden.
    size_t bbase  = (size_t)b * (NT_ * NX_);
    size_t pbase0 = bbase + (size_t)tile0 * POS_PER_TILE + (size_t)pg * POS_PER_PG;
    const float4* t4 = reinterpret_cast<const float4*>(t_coords + pbase0);
    const float4* x4 = reinterpret_cast<const float4*>(x_coords + pbase0);
    float4 T[4], X[4];
    #pragma unroll
    for (int c = 0; c < 4; ++c) { T[c] = __ldg(t4 + c); X[c] = __ldg(x4 + c); }

    // ---- Per-block Riemann solve: thread j < 63 handles interface j of b.
    if (t < NI_) {
        int j = t;
        const float gm1 = 0.4f;
        const float gp1 = 2.4f;
        const float exp_rare = gm1 / (2.0f * GAMMA_F);               // 1/7
        const float neg_exp  = -(GAMMA_F + 1.0f) / (2.0f * GAMMA_F); // -6/7

        float rho_L = ks  [b * K_ + j];
        float rho_R = ks  [b * K_ + j + 1];
        float u_L   = ks_v[b * K_ + j];
        float u_R   = ks_v[b * K_ + j + 1];
        float p_L   = ks_p[b * K_ + j];
        float p_R   = ks_p[b * K_ + j + 1];

        float pLc = fmaxf(p_L, EPS_F);
        float pRc = fmaxf(p_R, EPS_F);

        float c_L = sqrtf(fmaxf(GAMMA_F * p_L / fmaxf(rho_L, EPS_F), EPS_F));
        float c_R = sqrtf(fmaxf(GAMMA_F * p_R / fmaxf(rho_R, EPS_F), EPS_F));
        float A_L = 2.0f / (gp1 * fmaxf(rho_L, EPS_F));
        float A_R = 2.0f / (gp1 * fmaxf(rho_R, EPS_F));
        float B_L = gm1 / gp1 * p_L;
        float B_R = gm1 / gp1 * p_R;
        float invpL = __fdividef(1.0f, pLc);
        float invpR = __fdividef(1.0f, pRc);
        float cg_L  = c_L * invpL * (1.0f / GAMMA_F);
        float cg_R  = c_R * invpR * (1.0f / GAMMA_F);
        float tfc_L = 2.0f * c_L / gm1;
        float tfc_R = 2.0f * c_R / gm1;

        float du  = u_R - u_L;
        float num = c_L + c_R - 0.5f * gm1 * du;
        float den = c_L * fast_pow(pLc, -exp_rare) + c_R * fast_pow(pRc, -exp_rare);
        float r   = __fdividef(num, den);
        float r2  = r * r;
        float r4  = r2 * r2;
        float p_star = fmaxf(r4 * r2 * r, EPS_F);       // r^7

        #pragma unroll 1
        for (int it = 0; it < N_NEWTON; ++it) {
            float fL, dfL, fR, dfR;
            {
                float denom    = fmaxf(p_star + B_L, EPS_F);
                float sqrt_AoD = sqrtf(fmaxf(__fdividef(A_L, denom), EPS_F));
                float dl       = p_star - p_L;
                float f_shock  = dl * sqrt_AoD;
                float df_shock = sqrt_AoD * (1.0f - dl * __fdividef(0.5f, denom));
                float pratio   = fmaxf(p_star * invpL, EPS_F);
                float l2       = f_lg2(pratio);
                float f_rare   = tfc_L * (f_ex2(exp_rare * l2) - 1.0f);
                float df_rare  = cg_L * f_ex2(neg_exp * l2);
                bool  shock    = p_star > p_L;
                fL  = shock ? f_shock  : f_rare;
                dfL = shock ? df_shock : df_rare;
            }
            {
                float denom    = fmaxf(p_star + B_R, EPS_F);
                float sqrt_AoD = sqrtf(fmaxf(__fdividef(A_R, denom), EPS_F));
                float dr       = p_star - p_R;
                float f_shock  = dr * sqrt_AoD;
                float df_shock = sqrt_AoD * (1.0f - dr * __fdividef(0.5f, denom));
                float pratio   = fmaxf(p_star * invpR, EPS_F);
                float l2       = f_lg2(pratio);
                float f_rare   = tfc_R * (f_ex2(exp_rare * l2) - 1.0f);
                float df_rare  = cg_R * f_ex2(neg_exp * l2);
                bool  shock    = p_star > p_R;
                fR  = shock ? f_shock  : f_rare;
                dfR = shock ? df_shock : df_rare;
            }
            float residual = fL + fR + du;
            float jacobian = fmaxf(dfL + dfR, EPS_F);
            p_star = fmaxf(p_star - __fdividef(residual, jacobian), EPS_F);
        }

        const float gp1_o_2g = gp1 / (2.0f * GAMMA_F);
        float sig1 = u_L - c_L * sqrtf(fmaxf(1.0f + gp1_o_2g * (p_star * invpL - 1.0f), EPS_F));
        float speed_left = (p_star > p_L) ? sig1 : (u_L - c_L);
        float sig3 = u_R + c_R * sqrtf(fmaxf(1.0f + gp1_o_2g * (p_star * invpR - 1.0f), EPS_F));
        float speed_right = (p_star > p_R) ? sig3 : (u_R + c_R);

        s_sl[j] = speed_left;
        s_sr[j] = speed_right;
        s_xd[j] = xs[b * (K_ + 1) + j + 1];
    }
    if (t == NI_) { s_xd[NI_] = 0.0f; s_sr[NI_] = 1e30f; }
    if (t < K_) s_m[t] = pieces_mask[b * K_ + t];
    __syncthreads();

    // ---- Per-thread register tables (valid for BOTH tiles: same batch) ----
    int q  = t & (QUADS - 1);
    int k0 = q << 2;

    float xda[5];                          // xd[k0-1 .. k0+3]
    float slv[4], srv[4], negm[4], b0[4];  // sl[k-1], sr[k], -m[k], bias0[k]
    xda[0] = (k0 == 0) ? 0.0f : s_xd[k0 - 1];
    slv[0] = (k0 == 0) ? -1e30f : s_sl[k0 - 1];   // sentinel: pen_right(k=0)=0
    #pragma unroll
    for (int i = 1; i < 5; ++i) xda[i] = s_xd[k0 + i - 1];
    #pragma unroll
    for (int kk = 1; kk < 4; ++kk) slv[kk] = s_sl[k0 + kk - 1];
    #pragma unroll
    for (int kk = 0; kk < 4; ++kk) {
        srv[kk] = s_sr[k0 + kk];
        float m = s_m[k0 + kk];
        negm[kk] = -m;
        b0[kk]   = (m == 0.0f) ? -1e9f : 0.0f;
    }

    // ---- Tile loop (2 tiles) ----
    #pragma unroll
    for (int tile = 0; tile < TILES_PER_BLOCK; ++tile) {
        size_t pbase = pbase0 + (size_t)tile * POS_PER_TILE;
        if (tile > 0) {
            // Front-batch this tile's coordinates (overlaps prior tile's
            // store drain).
            const float4* t4n = reinterpret_cast<const float4*>(t_coords + pbase);
            const float4* x4n = reinterpret_cast<const float4*>(x_coords + pbase);
            #pragma unroll
            for (int c = 0; c < 4; ++c) { T[c] = __ldg(t4n + c); X[c] = __ldg(x4n + c); }
        }

        float* op = out + pbase * K_ + k0;

        #pragma unroll
        for (int c = 0; c < 4; ++c) {
            float tts[4] = {T[c].x, T[c].y, T[c].z, T[c].w};
            float xxs[4] = {X[c].x, X[c].y, X[c].z, X[c].w};

            #pragma unroll
            for (int p = 0; p < 4; ++p) {
                float te  = tts[p] + EPS_F;
                float xx  = xxs[p];
                float inv = __fdividef(1.0f, te);

                float d[5];
                #pragma unroll
                for (int i = 0; i < 5; ++i) d[i] = xx - xda[i];

                float vals[4];
                #pragma unroll
                for (int kk = 0; kk < 4; ++kk) {
                    float pl = fmaxf(fmaf(-srv[kk], te,  d[kk + 1]), 0.0f);
                    float pr = fmaxf(fmaf( slv[kk], te, -d[kk]),     0.0f);
                    vals[kk] = fmaf((pl + pr) * inv, negm[kk], b0[kk]);
                }
                __stcs(reinterpret_cast<float4*>(op + (size_t)(c * 4 + p) * K_),
                       make_float4(vals[0], vals[1], vals[2], vals[3]));
            }
        }
    }
}

// ---------------------------------------------------------------------------
// Launch. Inputs: 0:xs 1:ks 2:ks_v 3:ks_p 4:pieces_mask 5:t_coords 6:x_coords
// Single fused persistent-ish kernel launch (1024 blocks x 2 tiles).
// ---------------------------------------------------------------------------
extern "C" void kernel_launch(void* const* d_in, const int* in_sizes, int n_in,
                              void* d_out, int out_size) {
    const float* xs          = (const float*)d_in[0];
    const float* ks          = (const float*)d_in[1];
    const float* ks_v        = (const float*)d_in[2];
    const float* ks_p        = (const float*)d_in[3];
    const float* pieces_mask = (const float*)d_in[4];
    const float* t_coords    = (const float*)d_in[5];
    const float* x_coords    = (const float*)d_in[6];
    float* out = (float*)d_out;

    fused_bias_kernel<<<GRID, THREADS>>>(
        xs, ks, ks_v, ks_p, pieces_mask, t_coords, x_coords, out);
}

// round 16
// speedup vs baseline: 1.2766x; 1.1354x over previous
#include <cuda_runtime.h>
#include <math.h>

#define GAMMA_F 1.4f
#define EPS_F   1e-6f
constexpr int B_  = 16;
constexpr int K_  = 64;
constexpr int NT_ = 128;
constexpr int NX_ = 256;
constexpr int NI_ = K_ - 1;           // 63 interfaces per batch
constexpr int N_NEWTON = 8;           // quadratic convergence; fixed point by ~6

// Scratch for the star-state wave speeds (allocation-free: __device__ globals)
__device__ float g_speed_left [B_ * NI_];
__device__ float g_speed_right[B_ * NI_];

// MUFU transcendentals via inline PTX
__device__ __forceinline__ float f_lg2(float x) {
    float r;
    asm("lg2.approx.f32 %0, %1;" : "=f"(r) : "f"(x));
    return r;
}
__device__ __forceinline__ float f_ex2(float x) {
    float r;
    asm("ex2.approx.f32 %0, %1;" : "=f"(r) : "f"(x));
    return r;
}
__device__ __forceinline__ float fast_pow(float x, float e) {
    return f_ex2(e * f_lg2(x));
}

// ---------------------------------------------------------------------------
// Kernel 1: per-interface Riemann star-pressure Newton solve -> wave speeds.
// Signals PDL dependents immediately.
// ---------------------------------------------------------------------------
__global__ void riemann_speeds_kernel(const float* __restrict__ ks,
                                      const float* __restrict__ ks_v,
                                      const float* __restrict__ ks_p) {
    asm volatile("griddepcontrol.launch_dependents;");

    int i = blockIdx.x * blockDim.x + threadIdx.x;
    if (i >= B_ * NI_) return;
    int b = i / NI_;
    int j = i - b * NI_;

    const float gm1 = 0.4f;
    const float gp1 = 2.4f;
    const float exp_rare = gm1 / (2.0f * GAMMA_F);               // 1/7
    const float neg_exp  = -(GAMMA_F + 1.0f) / (2.0f * GAMMA_F); // -6/7

    float rho_L = ks  [b * K_ + j];
    float rho_R = ks  [b * K_ + j + 1];
    float u_L   = ks_v[b * K_ + j];
    float u_R   = ks_v[b * K_ + j + 1];
    float p_L   = ks_p[b * K_ + j];
    float p_R   = ks_p[b * K_ + j + 1];

    float pLc = fmaxf(p_L, EPS_F);
    float pRc = fmaxf(p_R, EPS_F);

    float c_L = sqrtf(fmaxf(GAMMA_F * p_L / fmaxf(rho_L, EPS_F), EPS_F));
    float c_R = sqrtf(fmaxf(GAMMA_F * p_R / fmaxf(rho_R, EPS_F), EPS_F));
    float A_L = 2.0f / (gp1 * fmaxf(rho_L, EPS_F));
    float A_R = 2.0f / (gp1 * fmaxf(rho_R, EPS_F));
    float B_L = gm1 / gp1 * p_L;
    float B_R = gm1 / gp1 * p_R;
    float invpL = __fdividef(1.0f, pLc);
    float invpR = __fdividef(1.0f, pRc);
    float cg_L  = c_L * invpL * (1.0f / GAMMA_F);
    float cg_R  = c_R * invpR * (1.0f / GAMMA_F);
    float tfc_L = 2.0f * c_L / gm1;
    float tfc_R = 2.0f * c_R / gm1;

    float du  = u_R - u_L;
    float num = c_L + c_R - 0.5f * gm1 * du;
    float den = c_L * fast_pow(pLc, -exp_rare) + c_R * fast_pow(pRc, -exp_rare);
    float r   = __fdividef(num, den);
    float r2  = r * r;
    float r4  = r2 * r2;
    float p_star = fmaxf(r4 * r2 * r, EPS_F);       // r^7

    #pragma unroll 1
    for (int it = 0; it < N_NEWTON; ++it) {
        float fL, dfL, fR, dfR;
        {
            float denom    = fmaxf(p_star + B_L, EPS_F);
            float sqrt_AoD = sqrtf(fmaxf(__fdividef(A_L, denom), EPS_F));
            float dl       = p_star - p_L;
            float f_shock  = dl * sqrt_AoD;
            float df_shock = sqrt_AoD * (1.0f - dl * __fdividef(0.5f, denom));
            float pratio   = fmaxf(p_star * invpL, EPS_F);
            float l2       = f_lg2(pratio);
            float f_rare   = tfc_L * (f_ex2(exp_rare * l2) - 1.0f);
            float df_rare  = cg_L * f_ex2(neg_exp * l2);
            bool  shock    = p_star > p_L;
            fL  = shock ? f_shock  : f_rare;
            dfL = shock ? df_shock : df_rare;
        }
        {
            float denom    = fmaxf(p_star + B_R, EPS_F);
            float sqrt_AoD = sqrtf(fmaxf(__fdividef(A_R, denom), EPS_F));
            float dr       = p_star - p_R;
            float f_shock  = dr * sqrt_AoD;
            float df_shock = sqrt_AoD * (1.0f - dr * __fdividef(0.5f, denom));
            float pratio   = fmaxf(p_star * invpR, EPS_F);
            float l2       = f_lg2(pratio);
            float f_rare   = tfc_R * (f_ex2(exp_rare * l2) - 1.0f);
            float df_rare  = cg_R * f_ex2(neg_exp * l2);
            bool  shock    = p_star > p_R;
            fR  = shock ? f_shock  : f_rare;
            dfR = shock ? df_shock : df_rare;
        }
        float residual = fL + fR + du;
        float jacobian = fmaxf(dfL + dfR, EPS_F);
        p_star = fmaxf(p_star - __fdividef(residual, jacobian), EPS_F);
    }

    const float gp1_o_2g = gp1 / (2.0f * GAMMA_F);
    float sig1 = u_L - c_L * sqrtf(fmaxf(1.0f + gp1_o_2g * (p_star * invpL - 1.0f), EPS_F));
    float speed_left = (p_star > p_L) ? sig1 : (u_L - c_L);
    float sig3 = u_R + c_R * sqrtf(fmaxf(1.0f + gp1_o_2g * (p_star * invpR - 1.0f), EPS_F));
    float speed_right = (p_star > p_R) ? sig3 : (u_R + c_R);

    g_speed_left [i] = speed_left;
    g_speed_right[i] = speed_right;
}

// ---------------------------------------------------------------------------
// Kernel 2: bias field (PDL dependent).
// R10 per-thread body (16 consecutive positions, 8 front-batched LDG.128,
// register K-tables, no occupancy cap) in a 128-thread block:
// 8 pgroups x 16 quads -> 128 positions/block, grid 4096 (fine granularity).
// ---------------------------------------------------------------------------
constexpr int THREADS = 128;
constexpr int QUADS = 16;                                // 16 quads cover K=64
constexpr int PGROUPS = THREADS / QUADS;                 // 8 pgroups
constexpr int POS_PER_PG = 16;                           // consecutive positions
constexpr int POS_PER_BLOCK = PGROUPS * POS_PER_PG;      // 128
constexpr int BLOCKS_PER_B  = (NT_ * NX_) / POS_PER_BLOCK;  // 256

__global__ __launch_bounds__(THREADS)
void bias_kernel(const float* __restrict__ xs,
                 const float* __restrict__ pieces_mask,
                 const float* __restrict__ t_coords,
                 const float* __restrict__ x_coords,
                 float* __restrict__ out) {
    __shared__ float s_xd[K_];   // s_xd[k] = xs[b,k+1] for k<63; s_xd[63] = 0 (pad)
    __shared__ float s_sl[NI_];
    __shared__ float s_sr[K_];   // s_sr[63] = +1e30 (pad: kills pen_left at k=63)
    __shared__ float s_m [K_];

    int b        = blockIdx.x >> 8;        // / BLOCKS_PER_B (=256)
    int blockInB = blockIdx.x & (BLOCKS_PER_B - 1);

    int t = threadIdx.x;

    // ---- Independent prologue (overlaps with riemann under PDL) ----
    size_t base   = (size_t)b * (NT_ * NX_) + (size_t)blockInB * POS_PER_BLOCK;
    int    pg     = t >> 4;
    size_t pbase  = base + (size_t)pg * POS_PER_PG;
    const float4* t4 = reinterpret_cast<const float4*>(t_coords + pbase);
    const float4* x4 = reinterpret_cast<const float4*>(x_coords + pbase);
    float4 T[4], X[4];
    #pragma unroll
    for (int c = 0; c < 4; ++c) { T[c] = __ldg(t4 + c); X[c] = __ldg(x4 + c); }

    if (t < NI_) s_xd[t] = xs[b * (K_ + 1) + t + 1];
    if (t == NI_) { s_xd[NI_] = 0.0f; s_sr[NI_] = 1e30f; }
    if (t < K_) s_m[t] = pieces_mask[b * K_ + t];

    // ---- Wait for riemann results, then read them ----
    asm volatile("griddepcontrol.wait;" ::: "memory");
    if (t < NI_) {
        s_sl[t] = g_speed_left [b * NI_ + t];
        s_sr[t] = g_speed_right[b * NI_ + t];
    }
    __syncthreads();

    int q  = t & (QUADS - 1);
    int k0 = q << 2;

    // Per-thread register tables
    float xda[5];                          // xd[k0-1 .. k0+3]
    float slv[4], srv[4], negm[4], b0[4];  // sl[k-1], sr[k], -m[k], bias0[k]
    xda[0] = (k0 == 0) ? 0.0f : s_xd[k0 - 1];
    slv[0] = (k0 == 0) ? -1e30f : s_sl[k0 - 1];   // sentinel: pen_right(k=0)=0
    #pragma unroll
    for (int i = 1; i < 5; ++i) xda[i] = s_xd[k0 + i - 1];
    #pragma unroll
    for (int kk = 1; kk < 4; ++kk) slv[kk] = s_sl[k0 + kk - 1];
    #pragma unroll
    for (int kk = 0; kk < 4; ++kk) {
        srv[kk] = s_sr[k0 + kk];
        float m = s_m[k0 + kk];
        negm[kk] = -m;
        b0[kk]   = (m == 0.0f) ? -1e9f : 0.0f;
    }

    float* op = out + pbase * K_ + k0;

    #pragma unroll
    for (int c = 0; c < 4; ++c) {
        float tts[4] = {T[c].x, T[c].y, T[c].z, T[c].w};
        float xxs[4] = {X[c].x, X[c].y, X[c].z, X[c].w};

        #pragma unroll
        for (int p = 0; p < 4; ++p) {
            float te  = tts[p] + EPS_F;
            float xx  = xxs[p];
            float inv = __fdividef(1.0f, te);

            float d[5];
            #pragma unroll
            for (int i = 0; i < 5; ++i) d[i] = xx - xda[i];

            float vals[4];
            #pragma unroll
            for (int kk = 0; kk < 4; ++kk) {
                float pl = fmaxf(fmaf(-srv[kk], te,  d[kk + 1]), 0.0f);
                float pr = fmaxf(fmaf( slv[kk], te, -d[kk]),     0.0f);
                vals[kk] = fmaf((pl + pr) * inv, negm[kk], b0[kk]);
            }
            __stcs(reinterpret_cast<float4*>(op + (size_t)(c * 4 + p) * K_),
                   make_float4(vals[0], vals[1], vals[2], vals[3]));
        }
    }
}

// ---------------------------------------------------------------------------
// Launch. Inputs: 0:xs 1:ks 2:ks_v 3:ks_p 4:pieces_mask 5:t_coords 6:x_coords
// Second launch uses PDL so the bias prologue overlaps the riemann kernel.
// ---------------------------------------------------------------------------
extern "C" void kernel_launch(void* const* d_in, const int* in_sizes, int n_in,
                              void* d_out, int out_size) {
    const float* xs          = (const float*)d_in[0];
    const float* ks          = (const float*)d_in[1];
    const float* ks_v        = (const float*)d_in[2];
    const float* ks_p        = (const float*)d_in[3];
    const float* pieces_mask = (const float*)d_in[4];
    const float* t_coords    = (const float*)d_in[5];
    const float* x_coords    = (const float*)d_in[6];
    float* out = (float*)d_out;

    int n_if = B_ * NI_;
    riemann_speeds_kernel<<<(n_if + 255) / 256, 256>>>(ks, ks_v, ks_p);

    cudaLaunchConfig_t cfg = {};
    cfg.gridDim  = dim3(B_ * BLOCKS_PER_B);   // 4096
    cfg.blockDim = dim3(THREADS);
    cudaLaunchAttribute attrs[1];
    attrs[0].id = cudaLaunchAttributeProgrammaticStreamSerialization;
    attrs[0].val.programmaticStreamSerializationAllowed = 1;
    cfg.attrs = attrs;
    cfg.numAttrs = 1;
    cudaLaunchKernelEx(&cfg, bias_kernel, xs, pieces_mask, t_coords, x_coords, out);
}

// round 17
// speedup vs baseline: 1.3241x; 1.0372x over previous
#include <cuda_runtime.h>
#include <math.h>

#define GAMMA_F 1.4f
#define EPS_F   1e-6f
constexpr int B_  = 16;
constexpr int K_  = 64;
constexpr int NT_ = 128;
constexpr int NX_ = 256;
constexpr int NI_ = K_ - 1;           // 63 interfaces per batch
constexpr int N_NEWTON = 8;           // quadratic convergence; fixed point by ~6

// Scratch for the star-state wave speeds (allocation-free: __device__ globals)
__device__ float g_speed_left [B_ * NI_];
__device__ float g_speed_right[B_ * NI_];

// MUFU transcendentals via inline PTX
__device__ __forceinline__ float f_lg2(float x) {
    float r;
    asm("lg2.approx.f32 %0, %1;" : "=f"(r) : "f"(x));
    return r;
}
__device__ __forceinline__ float f_ex2(float x) {
    float r;
    asm("ex2.approx.f32 %0, %1;" : "=f"(r) : "f"(x));
    return r;
}
__device__ __forceinline__ float fast_pow(float x, float e) {
    return f_ex2(e * f_lg2(x));
}

// ---------------------------------------------------------------------------
// Kernel 1: per-interface Riemann star-pressure Newton solve -> wave speeds.
// Signals PDL dependents immediately.
// ---------------------------------------------------------------------------
__global__ void riemann_speeds_kernel(const float* __restrict__ ks,
                                      const float* __restrict__ ks_v,
                                      const float* __restrict__ ks_p) {
    asm volatile("griddepcontrol.launch_dependents;");

    int i = blockIdx.x * blockDim.x + threadIdx.x;
    if (i >= B_ * NI_) return;
    int b = i / NI_;
    int j = i - b * NI_;

    const float gm1 = 0.4f;
    const float gp1 = 2.4f;
    const float exp_rare = gm1 / (2.0f * GAMMA_F);               // 1/7
    const float neg_exp  = -(GAMMA_F + 1.0f) / (2.0f * GAMMA_F); // -6/7

    float rho_L = ks  [b * K_ + j];
    float rho_R = ks  [b * K_ + j + 1];
    float u_L   = ks_v[b * K_ + j];
    float u_R   = ks_v[b * K_ + j + 1];
    float p_L   = ks_p[b * K_ + j];
    float p_R   = ks_p[b * K_ + j + 1];

    float pLc = fmaxf(p_L, EPS_F);
    float pRc = fmaxf(p_R, EPS_F);

    float c_L = sqrtf(fmaxf(GAMMA_F * p_L / fmaxf(rho_L, EPS_F), EPS_F));
    float c_R = sqrtf(fmaxf(GAMMA_F * p_R / fmaxf(rho_R, EPS_F), EPS_F));
    float A_L = 2.0f / (gp1 * fmaxf(rho_L, EPS_F));
    float A_R = 2.0f / (gp1 * fmaxf(rho_R, EPS_F));
    float B_L = gm1 / gp1 * p_L;
    float B_R = gm1 / gp1 * p_R;
    float invpL = __fdividef(1.0f, pLc);
    float invpR = __fdividef(1.0f, pRc);
    float cg_L  = c_L * invpL * (1.0f / GAMMA_F);
    float cg_R  = c_R * invpR * (1.0f / GAMMA_F);
    float tfc_L = 2.0f * c_L / gm1;
    float tfc_R = 2.0f * c_R / gm1;

    float du  = u_R - u_L;
    float num = c_L + c_R - 0.5f * gm1 * du;
    float den = c_L * fast_pow(pLc, -exp_rare) + c_R * fast_pow(pRc, -exp_rare);
    float r   = __fdividef(num, den);
    float r2  = r * r;
    float r4  = r2 * r2;
    float p_star = fmaxf(r4 * r2 * r, EPS_F);       // r^7

    #pragma unroll 1
    for (int it = 0; it < N_NEWTON; ++it) {
        float fL, dfL, fR, dfR;
        {
            float denom    = fmaxf(p_star + B_L, EPS_F);
            float sqrt_AoD = sqrtf(fmaxf(__fdividef(A_L, denom), EPS_F));
            float dl       = p_star - p_L;
            float f_shock  = dl * sqrt_AoD;
            float df_shock = sqrt_AoD * (1.0f - dl * __fdividef(0.5f, denom));
            float pratio   = fmaxf(p_star * invpL, EPS_F);
            float l2       = f_lg2(pratio);
            float f_rare   = tfc_L * (f_ex2(exp_rare * l2) - 1.0f);
            float df_rare  = cg_L * f_ex2(neg_exp * l2);
            bool  shock    = p_star > p_L;
            fL  = shock ? f_shock  : f_rare;
            dfL = shock ? df_shock : df_rare;
        }
        {
            float denom    = fmaxf(p_star + B_R, EPS_F);
            float sqrt_AoD = sqrtf(fmaxf(__fdividef(A_R, denom), EPS_F));
            float dr       = p_star - p_R;
            float f_shock  = dr * sqrt_AoD;
            float df_shock = sqrt_AoD * (1.0f - dr * __fdividef(0.5f, denom));
            float pratio   = fmaxf(p_star * invpR, EPS_F);
            float l2       = f_lg2(pratio);
            float f_rare   = tfc_R * (f_ex2(exp_rare * l2) - 1.0f);
            float df_rare  = cg_R * f_ex2(neg_exp * l2);
            bool  shock    = p_star > p_R;
            fR  = shock ? f_shock  : f_rare;
            dfR = shock ? df_shock : df_rare;
        }
        float residual = fL + fR + du;
        float jacobian = fmaxf(dfL + dfR, EPS_F);
        p_star = fmaxf(p_star - __fdividef(residual, jacobian), EPS_F);
    }

    const float gp1_o_2g = gp1 / (2.0f * GAMMA_F);
    float sig1 = u_L - c_L * sqrtf(fmaxf(1.0f + gp1_o_2g * (p_star * invpL - 1.0f), EPS_F));
    float speed_left = (p_star > p_L) ? sig1 : (u_L - c_L);
    float sig3 = u_R + c_R * sqrtf(fmaxf(1.0f + gp1_o_2g * (p_star * invpR - 1.0f), EPS_F));
    float speed_right = (p_star > p_R) ? sig3 : (u_R + c_R);

    g_speed_left [i] = speed_left;
    g_speed_right[i] = speed_right;
}

// ---------------------------------------------------------------------------
// Kernel 2: bias field (PDL dependent).
// R16 config + gentle occupancy nudge: __launch_bounds__(128, 8) caps regs
// at 64 (the compiler already hit 64 on this body at 256 threads, so no
// spill expected) -> 8 CTAs/SM = 1024 resident threads (+14% warps to hide
// STG.128 issue cost).
// ---------------------------------------------------------------------------
constexpr int THREADS = 128;
constexpr int QUADS = 16;                                // 16 quads cover K=64
constexpr int PGROUPS = THREADS / QUADS;                 // 8 pgroups
constexpr int POS_PER_PG = 16;                           // consecutive positions
constexpr int POS_PER_BLOCK = PGROUPS * POS_PER_PG;      // 128
constexpr int BLOCKS_PER_B  = (NT_ * NX_) / POS_PER_BLOCK;  // 256

__global__ __launch_bounds__(THREADS, 8)
void bias_kernel(const float* __restrict__ xs,
                 const float* __restrict__ pieces_mask,
                 const float* __restrict__ t_coords,
                 const float* __restrict__ x_coords,
                 float* __restrict__ out) {
    __shared__ float s_xd[K_];   // s_xd[k] = xs[b,k+1] for k<63; s_xd[63] = 0 (pad)
    __shared__ float s_sl[NI_];
    __shared__ float s_sr[K_];   // s_sr[63] = +1e30 (pad: kills pen_left at k=63)
    __shared__ float s_m [K_];

    int b        = blockIdx.x >> 8;        // / BLOCKS_PER_B (=256)
    int blockInB = blockIdx.x & (BLOCKS_PER_B - 1);

    int t = threadIdx.x;

    // ---- Independent prologue (overlaps with riemann under PDL) ----
    size_t base   = (size_t)b * (NT_ * NX_) + (size_t)blockInB * POS_PER_BLOCK;
    int    pg     = t >> 4;
    size_t pbase  = base + (size_t)pg * POS_PER_PG;
    const float4* t4 = reinterpret_cast<const float4*>(t_coords + pbase);
    const float4* x4 = reinterpret_cast<const float4*>(x_coords + pbase);
    float4 T[4], X[4];
    #pragma unroll
    for (int c = 0; c < 4; ++c) { T[c] = __ldg(t4 + c); X[c] = __ldg(x4 + c); }

    if (t < NI_) s_xd[t] = xs[b * (K_ + 1) + t + 1];
    if (t == NI_) { s_xd[NI_] = 0.0f; s_sr[NI_] = 1e30f; }
    if (t < K_) s_m[t] = pieces_mask[b * K_ + t];

    // ---- Wait for riemann results, then read them ----
    asm volatile("griddepcontrol.wait;" ::: "memory");
    if (t < NI_) {
        s_sl[t] = g_speed_left [b * NI_ + t];
        s_sr[t] = g_speed_right[b * NI_ + t];
    }
    __syncthreads();

    int q  = t & (QUADS - 1);
    int k0 = q << 2;

    // Per-thread register tables
    float xda[5];                          // xd[k0-1 .. k0+3]
    float slv[4], srv[4], negm[4], b0[4];  // sl[k-1], sr[k], -m[k], bias0[k]
    xda[0] = (k0 == 0) ? 0.0f : s_xd[k0 - 1];
    slv[0] = (k0 == 0) ? -1e30f : s_sl[k0 - 1];   // sentinel: pen_right(k=0)=0
    #pragma unroll
    for (int i = 1; i < 5; ++i) xda[i] = s_xd[k0 + i - 1];
    #pragma unroll
    for (int kk = 1; kk < 4; ++kk) slv[kk] = s_sl[k0 + kk - 1];
    #pragma unroll
    for (int kk = 0; kk < 4; ++kk) {
        srv[kk] = s_sr[k0 + kk];
        float m = s_m[k0 + kk];
        negm[kk] = -m;
        b0[kk]   = (m == 0.0f) ? -1e9f : 0.0f;
    }

    float* op = out + pbase * K_ + k0;

    #pragma unroll
    for (int c = 0; c < 4; ++c) {
        float tts[4] = {T[c].x, T[c].y, T[c].z, T[c].w};
        float xxs[4] = {X[c].x, X[c].y, X[c].z, X[c].w};

        #pragma unroll
        for (int p = 0; p < 4; ++p) {
            float te  = tts[p] + EPS_F;
            float xx  = xxs[p];
            float inv = __fdividef(1.0f, te);

            float d[5];
            #pragma unroll
            for (int i = 0; i < 5; ++i) d[i] = xx - xda[i];

            float vals[4];
            #pragma unroll
            for (int kk = 0; kk < 4; ++kk) {
                float pl = fmaxf(fmaf(-srv[kk], te,  d[kk + 1]), 0.0f);
                float pr = fmaxf(fmaf( slv[kk], te, -d[kk]),     0.0f);
                vals[kk] = fmaf((pl + pr) * inv, negm[kk], b0[kk]);
            }
            __stcs(reinterpret_cast<float4*>(op + (size_t)(c * 4 + p) * K_),
                   make_float4(vals[0], vals[1], vals[2], vals[3]));
        }
    }
}

// ---------------------------------------------------------------------------
// Launch. Inputs: 0:xs 1:ks 2:ks_v 3:ks_p 4:pieces_mask 5:t_coords 6:x_coords
// Second launch uses PDL so the bias prologue overlaps the riemann kernel.
// ---------------------------------------------------------------------------
extern "C" void kernel_launch(void* const* d_in, const int* in_sizes, int n_in,
                              void* d_out, int out_size) {
    const float* xs          = (const float*)d_in[0];
    const float* ks          = (const float*)d_in[1];
    const float* ks_v        = (const float*)d_in[2];
    const float* ks_p        = (const float*)d_in[3];
    const float* pieces_mask = (const float*)d_in[4];
    const float* t_coords    = (const float*)d_in[5];
    const float* x_coords    = (const float*)d_in[6];
    float* out = (float*)d_out;

    int n_if = B_ * NI_;
    riemann_speeds_kernel<<<(n_if + 255) / 256, 256>>>(ks, ks_v, ks_p);

    cudaLaunchConfig_t cfg = {};
    cfg.gridDim  = dim3(B_ * BLOCKS_PER_B);   // 4096
    cfg.blockDim = dim3(THREADS);
    cudaLaunchAttribute attrs[1];
    attrs[0].id = cudaLaunchAttributeProgrammaticStreamSerialization;
    attrs[0].val.programmaticStreamSerializationAllowed = 1;
    cfg.attrs = attrs;
    cfg.numAttrs = 1;
    cudaLaunchKernelEx(&cfg, bias_kernel, xs, pieces_mask, t_coords, x_coords, out);
}